// round 11
// baseline (speedup 1.0000x reference)
#include <cuda_runtime.h>
#include <cuda_fp16.h>
#include <math.h>
#include <stdint.h>

// ---------------------------------------------------------------------------
// Problem constants
// ---------------------------------------------------------------------------
#define DMODEL 1024
#define NHEAD  8
#define BQ     1024
#define NC     16384
#define HDIM   128
#define FHID   64

// GEMM tiling: 128x128 CTA tile, K chunks of 64, 3-stage cp.async ring
#define BM   128
#define BN   128
#define BKH  64
#define APAD 8
#define BPAD 8
#define NSTG 3

#define A_STG (BM * (BKH + APAD))          // halfs per A stage: 9216
#define BNN_STG (BKH * (BN + BPAD))        // halfs per B stage (NN): 8704
#define BNT_STG (BN * (BKH + APAD))        // halfs per B stage (NT): 9216

// ---------------------------------------------------------------------------
// Device scratch
// ---------------------------------------------------------------------------
__device__ float  g_dot  [(size_t)BQ * NC];
__device__ float  g_qsq  [BQ];
__device__ float  g_ksq  [NC];
__device__ float  g_rowmax[BQ * NHEAD];
__device__ float  g_rowrcp[BQ * NHEAD];

__device__ __half g_q16  [BQ * DMODEL];
__device__ __half g_c16  [NC * DMODEL];
__device__ __half g_tmp16[NC * DMODEL];
__device__ __half g_qp16 [BQ * DMODEL];
__device__ __half g_kp16 [NC * DMODEL];
__device__ __half g_qh16 [BQ * DMODEL];
__device__ __half g_kh16 [NC * DMODEL];
__device__ __half g_sc16 [(size_t)BQ * NHEAD * NC];
__device__ __half g_w16  [6 * DMODEL * DMODEL];

// ---------------------------------------------------------------------------
// PTX helpers
// ---------------------------------------------------------------------------
__device__ __forceinline__ uint32_t smem_u32(const void* p)
{
    return (uint32_t)__cvta_generic_to_shared(p);
}
__device__ __forceinline__ void cp16(const void* dst, const void* src)
{
    uint32_t d = smem_u32(dst);
    asm volatile("cp.async.cg.shared.global [%0], [%1], 16;\n" :: "r"(d), "l"(src));
}
__device__ __forceinline__ void cp_commit()
{
    asm volatile("cp.async.commit_group;\n");
}
__device__ __forceinline__ void cp_wait_n(int n)
{
    if (n <= 0)      asm volatile("cp.async.wait_group 0;\n");
    else             asm volatile("cp.async.wait_group 1;\n");
}
__device__ __forceinline__ void ldsm_x4(uint32_t& r0, uint32_t& r1, uint32_t& r2, uint32_t& r3,
                                        const void* p)
{
    uint32_t a = smem_u32(p);
    asm volatile("ldmatrix.sync.aligned.m8n8.x4.shared.b16 {%0,%1,%2,%3}, [%4];\n"
                 : "=r"(r0), "=r"(r1), "=r"(r2), "=r"(r3) : "r"(a));
}
__device__ __forceinline__ void ldsm_x4_t(uint32_t& r0, uint32_t& r1, uint32_t& r2, uint32_t& r3,
                                          const void* p)
{
    uint32_t a = smem_u32(p);
    asm volatile("ldmatrix.sync.aligned.m8n8.x4.trans.shared.b16 {%0,%1,%2,%3}, [%4];\n"
                 : "=r"(r0), "=r"(r1), "=r"(r2), "=r"(r3) : "r"(a));
}
__device__ __forceinline__ void mma16816(float* c, const uint32_t* a, const uint32_t* b)
{
    asm volatile("mma.sync.aligned.m16n8k16.row.col.f32.f16.f16.f32 "
                 "{%0,%1,%2,%3}, {%4,%5,%6,%7}, {%8,%9}, {%0,%1,%2,%3};\n"
                 : "+f"(c[0]), "+f"(c[1]), "+f"(c[2]), "+f"(c[3])
                 : "r"(a[0]), "r"(a[1]), "r"(a[2]), "r"(a[3]), "r"(b[0]), "r"(b[1]));
}

// ---------------------------------------------------------------------------
// HMMA GEMM, NN: C[M,N] = A16[M,K] @ B16[K,N] + bias
// wmode bit0: write fp32 C32, bit1: write fp16 C16. 3-stage ring, K=64 chunks.
// ---------------------------------------------------------------------------
__device__ __forceinline__ void nn_load_stage(
    __half* As, __half* Bs,
    const __half* A, const __half* B, int lda, int ldb,
    int br, int bc, int k0, int tid)
{
#pragma unroll
    for (int i = 0; i < 4; ++i) {          // A: 128 rows x 64 halfs
        const int idx = tid + i * 256;
        const int row = idx >> 3;
        const int c8  = (idx & 7) * 8;
        cp16(As + row * (BKH + APAD) + c8, A + (size_t)(br + row) * lda + k0 + c8);
    }
#pragma unroll
    for (int i = 0; i < 4; ++i) {          // B: 64 rows x 128 halfs
        const int idx = tid + i * 256;
        const int row = idx >> 4;
        const int c8  = (idx & 15) * 8;
        cp16(Bs + row * (BN + BPAD) + c8, B + (size_t)(k0 + row) * ldb + bc + c8);
    }
    cp_commit();
}

__global__ __launch_bounds__(256)
void gemm_nn16(const __half* __restrict__ A, const __half* __restrict__ B,
               const float* __restrict__ bias,
               float* __restrict__ C32, __half* __restrict__ C16,
               int K, int lda, int ldb, int ldc, int wmode)
{
    extern __shared__ __half sm[];
    __half* Asb = sm;                       // NSTG * A_STG
    __half* Bsb = sm + NSTG * A_STG;        // NSTG * BNN_STG

    const int tid  = threadIdx.x;
    const int br   = blockIdx.y * BM;
    const int bc   = blockIdx.x * BN;
    const int warp = tid >> 5, lane = tid & 31;
    const int wm   = (warp >> 2) * 64;
    const int wn   = (warp & 3) * 32;

    float acc[4][4][4];
#pragma unroll
    for (int i = 0; i < 4; ++i)
#pragma unroll
        for (int j = 0; j < 4; ++j)
#pragma unroll
            for (int r = 0; r < 4; ++r) acc[i][j][r] = 0.f;

    const int NCH = K / BKH;
    // prologue: load chunks 0 .. NSTG-2
#pragma unroll
    for (int c = 0; c < NSTG - 1; ++c)
        if (c < NCH)
            nn_load_stage(Asb + c * A_STG, Bsb + c * BNN_STG, A, B, lda, ldb, br, bc,
                          c * BKH, tid);

    for (int c = 0; c < NCH; ++c) {
        int rem = NCH - 1 - c;
        if (rem > NSTG - 2) rem = NSTG - 2;
        cp_wait_n(rem);
        __syncthreads();

        const int cn = c + NSTG - 1;
        if (cn < NCH) {
            const int s2 = cn % NSTG;
            nn_load_stage(Asb + s2 * A_STG, Bsb + s2 * BNN_STG, A, B, lda, ldb, br, bc,
                          cn * BKH, tid);
        }

        const int s = c % NSTG;
        __half* As = Asb + s * A_STG;
        __half* Bs = Bsb + s * BNN_STG;
#pragma unroll
        for (int ks = 0; ks < 4; ++ks) {
            uint32_t a[4][4], b[4][2];
#pragma unroll
            for (int mt = 0; mt < 4; ++mt)
                ldsm_x4(a[mt][0], a[mt][1], a[mt][2], a[mt][3],
                        As + (wm + mt * 16 + (lane & 15)) * (BKH + APAD)
                           + ks * 16 + (lane >> 4) * 8);
#pragma unroll
            for (int nt2 = 0; nt2 < 2; ++nt2) {
                const int kk = ks * 16 + (lane & 7) + ((lane >> 3) & 1) * 8;
                const int nn = wn + nt2 * 16 + (lane >> 4) * 8;
                ldsm_x4_t(b[nt2 * 2][0], b[nt2 * 2][1], b[nt2 * 2 + 1][0], b[nt2 * 2 + 1][1],
                          Bs + kk * (BN + BPAD) + nn);
            }
#pragma unroll
            for (int mt = 0; mt < 4; ++mt)
#pragma unroll
                for (int nt = 0; nt < 4; ++nt)
                    mma16816(acc[mt][nt], a[mt], b[nt]);
        }
    }

    const int g = lane >> 2, tig = lane & 3;
#pragma unroll
    for (int mt = 0; mt < 4; ++mt) {
#pragma unroll
        for (int nt = 0; nt < 4; ++nt) {
            const int row = br + wm + mt * 16 + g;
            const int col = bc + wn + nt * 8 + tig * 2;
            const float bx = bias[col], by = bias[col + 1];
            const float v00 = acc[mt][nt][0] + bx, v01 = acc[mt][nt][1] + by;
            const float v10 = acc[mt][nt][2] + bx, v11 = acc[mt][nt][3] + by;
            if (wmode & 1) {
                float2 u0 = make_float2(v00, v01);
                float2 u1 = make_float2(v10, v11);
                *reinterpret_cast<float2*>(&C32[(size_t)row * ldc + col]) = u0;
                *reinterpret_cast<float2*>(&C32[(size_t)(row + 8) * ldc + col]) = u1;
            }
            if (wmode & 2) {
                *reinterpret_cast<__half2*>(&C16[(size_t)row * ldc + col]) =
                    __floats2half2_rn(v00, v01);
                *reinterpret_cast<__half2*>(&C16[(size_t)(row + 8) * ldc + col]) =
                    __floats2half2_rn(v10, v11);
            }
        }
    }
}

// ---------------------------------------------------------------------------
// HMMA GEMM, NT: C[M,N] = alpha * A16[M,K] @ B16[N,K]^T, batched over z.
// ---------------------------------------------------------------------------
__device__ __forceinline__ void nt_load_stage(
    __half* As, __half* Bs,
    const __half* A, const __half* B, int lda, int ldb,
    int br, int bc, int k0, int tid)
{
#pragma unroll
    for (int i = 0; i < 4; ++i) {
        const int idx = tid + i * 256;
        const int row = idx >> 3;
        const int c8  = (idx & 7) * 8;
        cp16(As + row * (BKH + APAD) + c8, A + (size_t)(br + row) * lda + k0 + c8);
    }
#pragma unroll
    for (int i = 0; i < 4; ++i) {
        const int idx = tid + i * 256;
        const int row = idx >> 3;
        const int c8  = (idx & 7) * 8;
        cp16(Bs + row * (BKH + APAD) + c8, B + (size_t)(bc + row) * ldb + k0 + c8);
    }
    cp_commit();
}

__global__ __launch_bounds__(256)
void gemm_nt16(const __half* __restrict__ A, const __half* __restrict__ B,
               float* __restrict__ C32, __half* __restrict__ C16,
               int K, int lda, int ldb, int ldc,
               int azs, int bzs, int czs, float alpha, int f16out)
{
    extern __shared__ __half sm[];
    __half* Asb = sm;
    __half* Bsb = sm + NSTG * A_STG;

    const int tid  = threadIdx.x;
    const int br   = blockIdx.y * BM;
    const int bc   = blockIdx.x * BN;
    const int warp = tid >> 5, lane = tid & 31;
    const int wm   = (warp >> 2) * 64;
    const int wn   = (warp & 3) * 32;
    A   += (size_t)blockIdx.z * azs;
    B   += (size_t)blockIdx.z * bzs;
    C32 += (size_t)blockIdx.z * czs;
    C16 += (size_t)blockIdx.z * czs;

    float acc[4][4][4];
#pragma unroll
    for (int i = 0; i < 4; ++i)
#pragma unroll
        for (int j = 0; j < 4; ++j)
#pragma unroll
            for (int r = 0; r < 4; ++r) acc[i][j][r] = 0.f;

    const int NCH = K / BKH;
#pragma unroll
    for (int c = 0; c < NSTG - 1; ++c)
        if (c < NCH)
            nt_load_stage(Asb + c * A_STG, Bsb + c * BNT_STG, A, B, lda, ldb, br, bc,
                          c * BKH, tid);

    for (int c = 0; c < NCH; ++c) {
        int rem = NCH - 1 - c;
        if (rem > NSTG - 2) rem = NSTG - 2;
        cp_wait_n(rem);
        __syncthreads();

        const int cn = c + NSTG - 1;
        if (cn < NCH) {
            const int s2 = cn % NSTG;
            nt_load_stage(Asb + s2 * A_STG, Bsb + s2 * BNT_STG, A, B, lda, ldb, br, bc,
                          cn * BKH, tid);
        }

        const int s = c % NSTG;
        __half* As = Asb + s * A_STG;
        __half* Bs = Bsb + s * BNT_STG;
#pragma unroll
        for (int ks = 0; ks < 4; ++ks) {
            uint32_t a[4][4], b[4][2];
#pragma unroll
            for (int mt = 0; mt < 4; ++mt)
                ldsm_x4(a[mt][0], a[mt][1], a[mt][2], a[mt][3],
                        As + (wm + mt * 16 + (lane & 15)) * (BKH + APAD)
                           + ks * 16 + (lane >> 4) * 8);
#pragma unroll
            for (int nt2 = 0; nt2 < 2; ++nt2) {
                const int nn = wn + nt2 * 16 + (lane >> 4) * 8 + (lane & 7);
                const int kk = ks * 16 + ((lane >> 3) & 1) * 8;
                ldsm_x4(b[nt2 * 2][0], b[nt2 * 2][1], b[nt2 * 2 + 1][0], b[nt2 * 2 + 1][1],
                        Bs + nn * (BKH + APAD) + kk);
            }
#pragma unroll
            for (int mt = 0; mt < 4; ++mt)
#pragma unroll
                for (int nt = 0; nt < 4; ++nt)
                    mma16816(acc[mt][nt], a[mt], b[nt]);
        }
    }

    const int g = lane >> 2, tig = lane & 3;
#pragma unroll
    for (int mt = 0; mt < 4; ++mt) {
#pragma unroll
        for (int nt = 0; nt < 4; ++nt) {
            const int row = br + wm + mt * 16 + g;
            const int col = bc + wn + nt * 8 + tig * 2;
            const float v00 = acc[mt][nt][0] * alpha, v01 = acc[mt][nt][1] * alpha;
            const float v10 = acc[mt][nt][2] * alpha, v11 = acc[mt][nt][3] * alpha;
            if (f16out) {
                *reinterpret_cast<__half2*>(&C16[(size_t)row * ldc + col]) =
                    __floats2half2_rn(v00, v01);
                *reinterpret_cast<__half2*>(&C16[(size_t)(row + 8) * ldc + col]) =
                    __floats2half2_rn(v10, v11);
            } else {
                float2 u0 = make_float2(v00, v01);
                float2 u1 = make_float2(v10, v11);
                *reinterpret_cast<float2*>(&C32[(size_t)row * ldc + col]) = u0;
                *reinterpret_cast<float2*>(&C32[(size_t)(row + 8) * ldc + col]) = u1;
            }
        }
    }
}

// ---------------------------------------------------------------------------
// float -> half conversion (single tensor)
// ---------------------------------------------------------------------------
__global__ __launch_bounds__(256)
void f2h_kernel(const float* __restrict__ s, __half* __restrict__ d, int n)
{
    int i = (blockIdx.x * 256 + threadIdx.x) * 4;
    if (i < n) {
        float4 v = *reinterpret_cast<const float4*>(s + i);
        *reinterpret_cast<__half2*>(d + i)     = __floats2half2_rn(v.x, v.y);
        *reinterpret_cast<__half2*>(d + i + 2) = __floats2half2_rn(v.z, v.w);
    }
}

// ---------------------------------------------------------------------------
// Batched float -> half for the six DMODEL x DMODEL weight matrices
// ---------------------------------------------------------------------------
struct Ptr6 { const float* s[6]; };

__global__ __launch_bounds__(256)
void f2h_weights_kernel(Ptr6 src, __half* __restrict__ dst)
{
    const int WW = DMODEL * DMODEL;
    int i = (blockIdx.x * 256 + threadIdx.x) * 4;
    const int mat = i / WW;
    const int off = i - mat * WW;
    const float* sp = src.s[mat] + off;
    __half* dp = dst + (size_t)mat * WW + off;
    float4 v = *reinterpret_cast<const float4*>(sp);
    *reinterpret_cast<__half2*>(dp)     = __floats2half2_rn(v.x, v.y);
    *reinterpret_cast<__half2*>(dp + 2) = __floats2half2_rn(v.z, v.w);
}

// ---------------------------------------------------------------------------
// Fused LayerNorm + exact GELU, fp16 in -> fp16 out (in-place safe)
// ---------------------------------------------------------------------------
__global__ __launch_bounds__(256)
void ln_gelu_kernel(const __half* __restrict__ X, __half* __restrict__ Y,
                    const float* __restrict__ g, const float* __restrict__ be)
{
    const int row = blockIdx.x, tid = threadIdx.x;
    const __half2* x2 = reinterpret_cast<const __half2*>(X + (size_t)row * DMODEL) + tid * 2;
    float2 a0 = __half22float2(x2[0]);
    float2 a1 = __half22float2(x2[1]);
    float s  = a0.x + a0.y + a1.x + a1.y;
    float s2 = a0.x * a0.x + a0.y * a0.y + a1.x * a1.x + a1.y * a1.y;

    __shared__ float shs[32];
    __shared__ float shs2[32];
    __shared__ float bc[2];
#pragma unroll
    for (int o = 16; o > 0; o >>= 1) {
        s  += __shfl_xor_sync(0xffffffffu, s, o);
        s2 += __shfl_xor_sync(0xffffffffu, s2, o);
    }
    if ((tid & 31) == 0) { shs[tid >> 5] = s; shs2[tid >> 5] = s2; }
    __syncthreads();
    if (tid == 0) {
        float a = 0.f, b2 = 0.f;
        for (int i = 0; i < 8; ++i) { a += shs[i]; b2 += shs2[i]; }
        bc[0] = a  * (1.f / DMODEL);
        bc[1] = b2 * (1.f / DMODEL);
    }
    __syncthreads();
    const float mu  = bc[0];
    const float inv = rsqrtf(bc[1] - mu * mu + 1e-5f);

    const float4 gg = *reinterpret_cast<const float4*>(&g[tid * 4]);
    const float4 bb = *reinterpret_cast<const float4*>(&be[tid * 4]);

    float y, o0, o1, o2, o3;
    y = (a0.x - mu) * inv * gg.x + bb.x;  o0 = 0.5f * y * (1.f + erff(y * 0.70710678118654752f));
    y = (a0.y - mu) * inv * gg.y + bb.y;  o1 = 0.5f * y * (1.f + erff(y * 0.70710678118654752f));
    y = (a1.x - mu) * inv * gg.z + bb.z;  o2 = 0.5f * y * (1.f + erff(y * 0.70710678118654752f));
    y = (a1.y - mu) * inv * gg.w + bb.w;  o3 = 0.5f * y * (1.f + erff(y * 0.70710678118654752f));

    __half2* yp = reinterpret_cast<__half2*>(Y + (size_t)row * DMODEL) + tid * 2;
    yp[0] = __floats2half2_rn(o0, o1);
    yp[1] = __floats2half2_rn(o2, o3);
}

// ---------------------------------------------------------------------------
// Row sum-of-squares (fp16 input, fp32 accumulate)
// ---------------------------------------------------------------------------
__global__ __launch_bounds__(256)
void rowsq_kernel(const __half* __restrict__ X, float* __restrict__ out)
{
    const int row = blockIdx.x, tid = threadIdx.x;
    const __half2* x2 = reinterpret_cast<const __half2*>(X + (size_t)row * DMODEL) + tid * 2;
    float2 a0 = __half22float2(x2[0]);
    float2 a1 = __half22float2(x2[1]);
    float s = a0.x * a0.x + a0.y * a0.y + a1.x * a1.x + a1.y * a1.y;
    __shared__ float sh[32];
#pragma unroll
    for (int o = 16; o > 0; o >>= 1) s += __shfl_xor_sync(0xffffffffu, s, o);
    if ((tid & 31) == 0) sh[tid >> 5] = s;
    __syncthreads();
    if (tid == 0) {
        float a = 0.f;
        for (int i = 0; i < 8; ++i) a += sh[i];
        out[row] = a;
    }
}

// ---------------------------------------------------------------------------
// Softmax stats per (b,h) row of fp16 scores: max and 1/sum(exp)
// ---------------------------------------------------------------------------
__global__ __launch_bounds__(256)
void softmax_stats_kernel(const __half* __restrict__ S,
                          float* __restrict__ rmax, float* __restrict__ rrcp)
{
    const int row = blockIdx.x, tid = threadIdx.x;
    const __half2* s2 = reinterpret_cast<const __half2*>(S + (size_t)row * NC);
    __shared__ float sh[32];
    __shared__ float bc[1];

    float m = -INFINITY;
    float2 vals[32];
#pragma unroll
    for (int i = 0; i < 32; ++i) {
        vals[i] = __half22float2(s2[tid + i * 256]);
        m = fmaxf(m, fmaxf(vals[i].x, vals[i].y));
    }
#pragma unroll
    for (int o = 16; o > 0; o >>= 1) m = fmaxf(m, __shfl_xor_sync(0xffffffffu, m, o));
    if ((tid & 31) == 0) sh[tid >> 5] = m;
    __syncthreads();
    if (tid == 0) {
        float a = -INFINITY;
        for (int i = 0; i < 8; ++i) a = fmaxf(a, sh[i]);
        bc[0] = a;
    }
    __syncthreads();
    const float mx = bc[0];

    float sum = 0.f;
#pragma unroll
    for (int i = 0; i < 32; ++i)
        sum += expf(vals[i].x - mx) + expf(vals[i].y - mx);
    __syncthreads();
#pragma unroll
    for (int o = 16; o > 0; o >>= 1) sum += __shfl_xor_sync(0xffffffffu, sum, o);
    if ((tid & 31) == 0) sh[tid >> 5] = sum;
    __syncthreads();
    if (tid == 0) {
        float a = 0.f;
        for (int i = 0; i < 8; ++i) a += sh[i];
        rmax[row] = mx;
        rrcp[row] = 1.f / a;
    }
}

// ---------------------------------------------------------------------------
// Fused epilogue: similarities -> MLP -> sigmoid
// ---------------------------------------------------------------------------
__global__ __launch_bounds__(256)
void fuse_kernel(const float* __restrict__ dot, const __half* __restrict__ scores,
                 const float* __restrict__ qsq, const float* __restrict__ ksq,
                 const float* __restrict__ rmax, const float* __restrict__ rrcp,
                 const float* __restrict__ temp,
                 const float* __restrict__ fw1, const float* __restrict__ fb1,
                 const float* __restrict__ fw2, const float* __restrict__ fb2,
                 float* __restrict__ out)
{
    __shared__ float w1[3][FHID];
    __shared__ float b1s[FHID];
    __shared__ float w2s[FHID];
    const int tid = threadIdx.x;
    if (tid < 3 * FHID) w1[tid / FHID][tid % FHID] = fw1[tid];
    if (tid < FHID) { b1s[tid] = fb1[tid]; w2s[tid] = fw2[tid]; }
    __syncthreads();

    const int b = blockIdx.y;
    const int n = blockIdx.x * 256 + tid;
    const float expT = expf(temp[0]);

    const float d  = dot[(size_t)b * NC + n];
    const float qs = qsq[b];
    const float ks = ksq[n];

    const float cs = d * rsqrtf(qs * ks) * expT;
    const float d2 = fmaxf(qs + ks - 2.f * d, 0.f);
    const float eu = 1.f / (1.f + sqrtf(d2));

    float ls = 0.f;
#pragma unroll
    for (int h = 0; h < NHEAD; ++h) {
        const int r = b * NHEAD + h;
        ls += expf(__half2float(scores[(size_t)r * NC + n]) - rmax[r]) * rrcp[r];
    }
    ls *= (1.f / NHEAD);

    float logit = fb2[0];
#pragma unroll
    for (int j = 0; j < FHID; ++j) {
        float hj = fmaf(cs, w1[0][j], fmaf(eu, w1[1][j], fmaf(ls, w1[2][j], b1s[j])));
        logit = fmaf(fmaxf(hj, 0.f), w2s[j], logit);
    }
    out[(size_t)b * NC + n] = 1.f / (1.f + expf(-logit));
}

// ---------------------------------------------------------------------------
// Host launcher
// ---------------------------------------------------------------------------
extern "C" void kernel_launch(void* const* d_in, const int* in_sizes, int n_in,
                              void* d_out, int out_size)
{
    const float* query = (const float*)d_in[0];
    const float* cand  = (const float*)d_in[1];
    const float* temp  = (const float*)d_in[2];
    const float* q_w1  = (const float*)d_in[3];
    const float* q_b1  = (const float*)d_in[4];
    const float* q_g   = (const float*)d_in[5];
    const float* q_be  = (const float*)d_in[6];
    const float* q_w2  = (const float*)d_in[7];
    const float* q_b2  = (const float*)d_in[8];
    const float* k_w1  = (const float*)d_in[9];
    const float* k_b1  = (const float*)d_in[10];
    const float* k_g   = (const float*)d_in[11];
    const float* k_be  = (const float*)d_in[12];
    const float* k_w2  = (const float*)d_in[13];
    const float* k_b2  = (const float*)d_in[14];
    const float* wq    = (const float*)d_in[15];
    const float* bq    = (const float*)d_in[16];
    const float* wk    = (const float*)d_in[17];
    const float* bk    = (const float*)d_in[18];
    const float* f_w1  = (const float*)d_in[19];
    const float* f_b1  = (const float*)d_in[20];
    const float* f_w2  = (const float*)d_in[21];
    const float* f_b2  = (const float*)d_in[22];
    float* out = (float*)d_out;

    float*  dotb  = 0;
    float*  qsq   = 0;
    float*  ksq   = 0;
    float*  rm    = 0;
    float*  rr    = 0;
    __half* q16   = 0;
    __half* c16   = 0;
    __half* tmp16 = 0;
    __half* qp16  = 0;
    __half* kp16  = 0;
    __half* qh16  = 0;
    __half* kh16  = 0;
    __half* sc16  = 0;
    __half* w16   = 0;

    cudaGetSymbolAddress((void**)&dotb,  g_dot);
    cudaGetSymbolAddress((void**)&qsq,   g_qsq);
    cudaGetSymbolAddress((void**)&ksq,   g_ksq);
    cudaGetSymbolAddress((void**)&rm,    g_rowmax);
    cudaGetSymbolAddress((void**)&rr,    g_rowrcp);
    cudaGetSymbolAddress((void**)&q16,   g_q16);
    cudaGetSymbolAddress((void**)&c16,   g_c16);
    cudaGetSymbolAddress((void**)&tmp16, g_tmp16);
    cudaGetSymbolAddress((void**)&qp16,  g_qp16);
    cudaGetSymbolAddress((void**)&kp16,  g_kp16);
    cudaGetSymbolAddress((void**)&qh16,  g_qh16);
    cudaGetSymbolAddress((void**)&kh16,  g_kh16);
    cudaGetSymbolAddress((void**)&sc16,  g_sc16);
    cudaGetSymbolAddress((void**)&w16,   g_w16);

    const int WW = DMODEL * DMODEL;
    __half* qw1_16 = w16 + 0 * WW;
    __half* qw2_16 = w16 + 1 * WW;
    __half* kw1_16 = w16 + 2 * WW;
    __half* kw2_16 = w16 + 3 * WW;
    __half* wq_16  = w16 + 4 * WW;
    __half* wk_16  = w16 + 5 * WW;

    const int SM_NN = NSTG * (A_STG + BNN_STG) * (int)sizeof(__half);   // 107520 B
    const int SM_NT = NSTG * (A_STG + BNT_STG) * (int)sizeof(__half);   // 110592 B
    cudaFuncSetAttribute(gemm_nn16, cudaFuncAttributeMaxDynamicSharedMemorySize, SM_NN);
    cudaFuncSetAttribute(gemm_nt16, cudaFuncAttributeMaxDynamicSharedMemorySize, SM_NT);

    const dim3 thr(256);
    const dim3 gq(DMODEL / BN, BQ / BM);
    const dim3 gk(DMODEL / BN, NC / BM);
    const float inv_sqrt_hd = 0.08838834764831845f;  // 1/sqrt(128)

    // launch 0: all six weight matrices in one conversion kernel
    Ptr6 wsrc;
    wsrc.s[0] = q_w1; wsrc.s[1] = q_w2; wsrc.s[2] = k_w1;
    wsrc.s[3] = k_w2; wsrc.s[4] = wq;   wsrc.s[5] = wk;
    f2h_weights_kernel<<<(6 * WW) / 1024, thr>>>(wsrc, w16);
    // launches 1-2: input conversions
    f2h_kernel<<<(BQ * DMODEL) / 1024, thr>>>(query, q16, BQ * DMODEL);
    f2h_kernel<<<(NC * DMODEL) / 1024, thr>>>(cand,  c16, NC * DMODEL);

    // launches 3-5: key projection chain — launch 5 is the profiled big GEMM
    gemm_nn16<<<gk, thr, SM_NN>>>(c16, kw1_16, k_b1, (float*)0, tmp16,
                                  DMODEL, DMODEL, DMODEL, DMODEL, 2);
    ln_gelu_kernel<<<NC, thr>>>(tmp16, tmp16, k_g, k_be);
    gemm_nn16<<<gk, thr, SM_NN>>>(tmp16, kw2_16, k_b2, (float*)0, kp16,
                                  DMODEL, DMODEL, DMODEL, DMODEL, 2);

    // query projection chain
    gemm_nn16<<<gq, thr, SM_NN>>>(q16, qw1_16, q_b1, (float*)0, tmp16,
                                  DMODEL, DMODEL, DMODEL, DMODEL, 2);
    ln_gelu_kernel<<<BQ, thr>>>(tmp16, tmp16, q_g, q_be);
    gemm_nn16<<<gq, thr, SM_NN>>>(tmp16, qw2_16, q_b2, (float*)0, qp16,
                                  DMODEL, DMODEL, DMODEL, DMODEL, 2);

    // MHA head projections
    gemm_nn16<<<gk, thr, SM_NN>>>(kp16, wk_16, bk, (float*)0, kh16,
                                  DMODEL, DMODEL, DMODEL, DMODEL, 2);
    gemm_nn16<<<gq, thr, SM_NN>>>(qp16, wq_16, bq, (float*)0, qh16,
                                  DMODEL, DMODEL, DMODEL, DMODEL, 2);

    // norms (fp16 in, fp32 accumulate)
    rowsq_kernel<<<BQ, thr>>>(qp16, qsq);
    rowsq_kernel<<<NC, thr>>>(kp16, ksq);

    // dot = qp @ kp^T (fp32 out)
    gemm_nt16<<<dim3(NC / BN, BQ / BM, 1), thr, SM_NT>>>(qp16, kp16, dotb, (__half*)0,
                                                         DMODEL, DMODEL, DMODEL, NC,
                                                         0, 0, 0, 1.f, 0);

    // per-head scores (fp16 out), layout [B][H][N]
    gemm_nt16<<<dim3(NC / BN, BQ / BM, NHEAD), thr, SM_NT>>>(qh16, kh16, (float*)0, sc16,
                                                             HDIM, DMODEL, DMODEL, NHEAD * NC,
                                                             HDIM, HDIM, NC, inv_sqrt_hd, 1);

    // softmax statistics per (b,h)
    softmax_stats_kernel<<<BQ * NHEAD, thr>>>(sc16, rm, rr);

    // fused similarity + MLP + sigmoid
    fuse_kernel<<<dim3(NC / 256, BQ), thr>>>(dotb, sc16, qsq, ksq, rm, rr, temp,
                                             f_w1, f_b1, f_w2, f_b2, out);
}

// round 13
// speedup vs baseline: 1.0333x; 1.0333x over previous
#include <cuda_runtime.h>
#include <cuda_fp16.h>
#include <math.h>
#include <stdint.h>

// ---------------------------------------------------------------------------
// Problem constants
// ---------------------------------------------------------------------------
#define DMODEL 1024
#define NHEAD  8
#define BQ     1024
#define NC     16384
#define HDIM   128
#define FHID   64

// GEMM tiling: 128x128 CTA tile, K chunks of 64, double-buffered cp.async (R9 config)
#define BM   128
#define BN   128
#define BKH  64
#define APAD 8
#define BPAD 8
#define NSTG 2

#define A_STG (BM * (BKH + APAD))          // halfs per A stage: 9216
#define BNN_STG (BKH * (BN + BPAD))        // halfs per B stage (NN): 8704
#define BNT_STG (BN * (BKH + APAD))        // halfs per B stage (NT): 9216

// ---------------------------------------------------------------------------
// Device scratch
// ---------------------------------------------------------------------------
__device__ float  g_dot  [(size_t)BQ * NC];
__device__ float  g_qsq  [BQ];
__device__ float  g_ksq  [NC];
__device__ float  g_rowsum[BQ * NHEAD];    // per-(b,h) sum of exp(scores)

__device__ __half g_q16  [BQ * DMODEL];
__device__ __half g_c16  [NC * DMODEL];
__device__ __half g_tmp16[NC * DMODEL];
__device__ __half g_qp16 [BQ * DMODEL];
__device__ __half g_kp16 [NC * DMODEL];
__device__ __half g_qh16 [BQ * DMODEL];
__device__ __half g_kh16 [NC * DMODEL];
__device__ __half g_sc16 [(size_t)BQ * NHEAD * NC];
__device__ __half g_w16  [6 * DMODEL * DMODEL];

// ---------------------------------------------------------------------------
// PTX helpers
// ---------------------------------------------------------------------------
__device__ __forceinline__ uint32_t smem_u32(const void* p)
{
    return (uint32_t)__cvta_generic_to_shared(p);
}
__device__ __forceinline__ void cp16(const void* dst, const void* src)
{
    uint32_t d = smem_u32(dst);
    asm volatile("cp.async.cg.shared.global [%0], [%1], 16;\n" :: "r"(d), "l"(src));
}
__device__ __forceinline__ void cp_commit()
{
    asm volatile("cp.async.commit_group;\n");
}
__device__ __forceinline__ void cp_wait0()
{
    asm volatile("cp.async.wait_group 0;\n");
}
__device__ __forceinline__ void ldsm_x4(uint32_t& r0, uint32_t& r1, uint32_t& r2, uint32_t& r3,
                                        const void* p)
{
    uint32_t a = smem_u32(p);
    asm volatile("ldmatrix.sync.aligned.m8n8.x4.shared.b16 {%0,%1,%2,%3}, [%4];\n"
                 : "=r"(r0), "=r"(r1), "=r"(r2), "=r"(r3) : "r"(a));
}
__device__ __forceinline__ void ldsm_x4_t(uint32_t& r0, uint32_t& r1, uint32_t& r2, uint32_t& r3,
                                          const void* p)
{
    uint32_t a = smem_u32(p);
    asm volatile("ldmatrix.sync.aligned.m8n8.x4.trans.shared.b16 {%0,%1,%2,%3}, [%4];\n"
                 : "=r"(r0), "=r"(r1), "=r"(r2), "=r"(r3) : "r"(a));
}
__device__ __forceinline__ void mma16816(float* c, const uint32_t* a, const uint32_t* b)
{
    asm volatile("mma.sync.aligned.m16n8k16.row.col.f32.f16.f16.f32 "
                 "{%0,%1,%2,%3}, {%4,%5,%6,%7}, {%8,%9}, {%0,%1,%2,%3};\n"
                 : "+f"(c[0]), "+f"(c[1]), "+f"(c[2]), "+f"(c[3])
                 : "r"(a[0]), "r"(a[1]), "r"(a[2]), "r"(a[3]), "r"(b[0]), "r"(b[1]));
}

// ---------------------------------------------------------------------------
// HMMA GEMM, NN: C[M,N] = A16[M,K] @ B16[K,N] + bias
// wmode bit0: write fp32 C32, bit1: write fp16 C16. Double-buffered, K=64 chunks.
// ---------------------------------------------------------------------------
__device__ __forceinline__ void nn_load_stage(
    __half* As, __half* Bs,
    const __half* A, const __half* B, int lda, int ldb,
    int br, int bc, int k0, int tid)
{
#pragma unroll
    for (int i = 0; i < 4; ++i) {          // A: 128 rows x 64 halfs
        const int idx = tid + i * 256;
        const int row = idx >> 3;
        const int c8  = (idx & 7) * 8;
        cp16(As + row * (BKH + APAD) + c8, A + (size_t)(br + row) * lda + k0 + c8);
    }
#pragma unroll
    for (int i = 0; i < 4; ++i) {          // B: 64 rows x 128 halfs
        const int idx = tid + i * 256;
        const int row = idx >> 4;
        const int c8  = (idx & 15) * 8;
        cp16(Bs + row * (BN + BPAD) + c8, B + (size_t)(k0 + row) * ldb + bc + c8);
    }
    cp_commit();
}

__global__ __launch_bounds__(256)
void gemm_nn16(const __half* __restrict__ A, const __half* __restrict__ B,
               const float* __restrict__ bias,
               float* __restrict__ C32, __half* __restrict__ C16,
               int K, int lda, int ldb, int ldc, int wmode)
{
    extern __shared__ __half sm[];
    __half* Asb = sm;                       // NSTG * A_STG
    __half* Bsb = sm + NSTG * A_STG;        // NSTG * BNN_STG

    const int tid  = threadIdx.x;
    const int br   = blockIdx.y * BM;
    const int bc   = blockIdx.x * BN;
    const int warp = tid >> 5, lane = tid & 31;
    const int wm   = (warp >> 2) * 64;
    const int wn   = (warp & 3) * 32;

    float acc[4][4][4];
#pragma unroll
    for (int i = 0; i < 4; ++i)
#pragma unroll
        for (int j = 0; j < 4; ++j)
#pragma unroll
            for (int r = 0; r < 4; ++r) acc[i][j][r] = 0.f;

    const int NCH = K / BKH;
    nn_load_stage(Asb, Bsb, A, B, lda, ldb, br, bc, 0, tid);

    for (int c = 0; c < NCH; ++c) {
        cp_wait0();
        __syncthreads();

        if (c + 1 < NCH) {
            const int s2 = (c + 1) & 1;
            nn_load_stage(Asb + s2 * A_STG, Bsb + s2 * BNN_STG, A, B, lda, ldb, br, bc,
                          (c + 1) * BKH, tid);
        }

        const int s = c & 1;
        __half* As = Asb + s * A_STG;
        __half* Bs = Bsb + s * BNN_STG;
#pragma unroll
        for (int ks = 0; ks < 4; ++ks) {
            uint32_t a[4][4], b[4][2];
#pragma unroll
            for (int mt = 0; mt < 4; ++mt)
                ldsm_x4(a[mt][0], a[mt][1], a[mt][2], a[mt][3],
                        As + (wm + mt * 16 + (lane & 15)) * (BKH + APAD)
                           + ks * 16 + (lane >> 4) * 8);
#pragma unroll
            for (int nt2 = 0; nt2 < 2; ++nt2) {
                const int kk = ks * 16 + (lane & 7) + ((lane >> 3) & 1) * 8;
                const int nn = wn + nt2 * 16 + (lane >> 4) * 8;
                ldsm_x4_t(b[nt2 * 2][0], b[nt2 * 2][1], b[nt2 * 2 + 1][0], b[nt2 * 2 + 1][1],
                          Bs + kk * (BN + BPAD) + nn);
            }
#pragma unroll
            for (int mt = 0; mt < 4; ++mt)
#pragma unroll
                for (int nt = 0; nt < 4; ++nt)
                    mma16816(acc[mt][nt], a[mt], b[nt]);
        }
    }

    const int g = lane >> 2, tig = lane & 3;
#pragma unroll
    for (int mt = 0; mt < 4; ++mt) {
#pragma unroll
        for (int nt = 0; nt < 4; ++nt) {
            const int row = br + wm + mt * 16 + g;
            const int col = bc + wn + nt * 8 + tig * 2;
            const float bx = bias[col], by = bias[col + 1];
            const float v00 = acc[mt][nt][0] + bx, v01 = acc[mt][nt][1] + by;
            const float v10 = acc[mt][nt][2] + bx, v11 = acc[mt][nt][3] + by;
            if (wmode & 1) {
                float2 u0 = make_float2(v00, v01);
                float2 u1 = make_float2(v10, v11);
                *reinterpret_cast<float2*>(&C32[(size_t)row * ldc + col]) = u0;
                *reinterpret_cast<float2*>(&C32[(size_t)(row + 8) * ldc + col]) = u1;
            }
            if (wmode & 2) {
                *reinterpret_cast<__half2*>(&C16[(size_t)row * ldc + col]) =
                    __floats2half2_rn(v00, v01);
                *reinterpret_cast<__half2*>(&C16[(size_t)(row + 8) * ldc + col]) =
                    __floats2half2_rn(v10, v11);
            }
        }
    }
}

// ---------------------------------------------------------------------------
// HMMA GEMM, NT: C[M,N] = alpha * A16[M,K] @ B16[N,K]^T, batched over z.
// f16out: fp16 vs fp32 C. do_sumexp: also atomicAdd per-row sum of exp(C)
// into rowsum[global_row * NHEAD + z] (scores softmax denominator; scores
// are O(1) so no max-subtraction is needed for fp32 exp safety).
// ---------------------------------------------------------------------------
__device__ __forceinline__ void nt_load_stage(
    __half* As, __half* Bs,
    const __half* A, const __half* B, int lda, int ldb,
    int br, int bc, int k0, int tid)
{
#pragma unroll
    for (int i = 0; i < 4; ++i) {
        const int idx = tid + i * 256;
        const int row = idx >> 3;
        const int c8  = (idx & 7) * 8;
        cp16(As + row * (BKH + APAD) + c8, A + (size_t)(br + row) * lda + k0 + c8);
    }
#pragma unroll
    for (int i = 0; i < 4; ++i) {
        const int idx = tid + i * 256;
        const int row = idx >> 3;
        const int c8  = (idx & 7) * 8;
        cp16(Bs + row * (BKH + APAD) + c8, B + (size_t)(bc + row) * ldb + k0 + c8);
    }
    cp_commit();
}

__global__ __launch_bounds__(256)
void gemm_nt16(const __half* __restrict__ A, const __half* __restrict__ B,
               float* __restrict__ C32, __half* __restrict__ C16,
               float* __restrict__ rowsum,
               int K, int lda, int ldb, int ldc,
               int azs, int bzs, int czs, float alpha, int f16out, int do_sumexp)
{
    extern __shared__ __half sm[];
    __half* Asb = sm;
    __half* Bsb = sm + NSTG * A_STG;

    const int tid  = threadIdx.x;
    const int br   = blockIdx.y * BM;
    const int bc   = blockIdx.x * BN;
    const int warp = tid >> 5, lane = tid & 31;
    const int wm   = (warp >> 2) * 64;
    const int wn   = (warp & 3) * 32;
    const int zid  = blockIdx.z;
    A   += (size_t)zid * azs;
    B   += (size_t)zid * bzs;
    C32 += (size_t)zid * czs;
    C16 += (size_t)zid * czs;

    float acc[4][4][4];
#pragma unroll
    for (int i = 0; i < 4; ++i)
#pragma unroll
        for (int j = 0; j < 4; ++j)
#pragma unroll
            for (int r = 0; r < 4; ++r) acc[i][j][r] = 0.f;

    const int NCH = K / BKH;
    nt_load_stage(Asb, Bsb, A, B, lda, ldb, br, bc, 0, tid);

    for (int c = 0; c < NCH; ++c) {
        cp_wait0();
        __syncthreads();

        if (c + 1 < NCH) {
            const int s2 = (c + 1) & 1;
            nt_load_stage(Asb + s2 * A_STG, Bsb + s2 * BNT_STG, A, B, lda, ldb, br, bc,
                          (c + 1) * BKH, tid);
        }

        const int s = c & 1;
        __half* As = Asb + s * A_STG;
        __half* Bs = Bsb + s * BNT_STG;
#pragma unroll
        for (int ks = 0; ks < 4; ++ks) {
            uint32_t a[4][4], b[4][2];
#pragma unroll
            for (int mt = 0; mt < 4; ++mt)
                ldsm_x4(a[mt][0], a[mt][1], a[mt][2], a[mt][3],
                        As + (wm + mt * 16 + (lane & 15)) * (BKH + APAD)
                           + ks * 16 + (lane >> 4) * 8);
#pragma unroll
            for (int nt2 = 0; nt2 < 2; ++nt2) {
                const int nn = wn + nt2 * 16 + (lane >> 4) * 8 + (lane & 7);
                const int kk = ks * 16 + ((lane >> 3) & 1) * 8;
                ldsm_x4(b[nt2 * 2][0], b[nt2 * 2][1], b[nt2 * 2 + 1][0], b[nt2 * 2 + 1][1],
                        Bs + nn * (BKH + APAD) + kk);
            }
#pragma unroll
            for (int mt = 0; mt < 4; ++mt)
#pragma unroll
                for (int nt = 0; nt < 4; ++nt)
                    mma16816(acc[mt][nt], a[mt], b[nt]);
        }
    }

    const int g = lane >> 2, tig = lane & 3;
#pragma unroll
    for (int mt = 0; mt < 4; ++mt) {
        float e0 = 0.f, e1 = 0.f;
#pragma unroll
        for (int nt = 0; nt < 4; ++nt) {
            const int row = br + wm + mt * 16 + g;
            const int col = bc + wn + nt * 8 + tig * 2;
            const float v00 = acc[mt][nt][0] * alpha, v01 = acc[mt][nt][1] * alpha;
            const float v10 = acc[mt][nt][2] * alpha, v11 = acc[mt][nt][3] * alpha;
            if (f16out) {
                *reinterpret_cast<__half2*>(&C16[(size_t)row * ldc + col]) =
                    __floats2half2_rn(v00, v01);
                *reinterpret_cast<__half2*>(&C16[(size_t)(row + 8) * ldc + col]) =
                    __floats2half2_rn(v10, v11);
            } else {
                float2 u0 = make_float2(v00, v01);
                float2 u1 = make_float2(v10, v11);
                *reinterpret_cast<float2*>(&C32[(size_t)row * ldc + col]) = u0;
                *reinterpret_cast<float2*>(&C32[(size_t)(row + 8) * ldc + col]) = u1;
            }
            if (do_sumexp) {
                e0 += expf(v00) + expf(v01);
                e1 += expf(v10) + expf(v11);
            }
        }
        if (do_sumexp) {
            // reduce across the 4 lanes (tig) that share each row
            e0 += __shfl_xor_sync(0xffffffffu, e0, 1);
            e0 += __shfl_xor_sync(0xffffffffu, e0, 2);
            e1 += __shfl_xor_sync(0xffffffffu, e1, 1);
            e1 += __shfl_xor_sync(0xffffffffu, e1, 2);
            if (tig == 0) {
                const int row = br + wm + mt * 16 + g;
                atomicAdd(&rowsum[(size_t)row * NHEAD + zid], e0);
                atomicAdd(&rowsum[(size_t)(row + 8) * NHEAD + zid], e1);
            }
        }
    }
}

// ---------------------------------------------------------------------------
// float -> half conversion (single tensor)
// ---------------------------------------------------------------------------
__global__ __launch_bounds__(256)
void f2h_kernel(const float* __restrict__ s, __half* __restrict__ d, int n)
{
    int i = (blockIdx.x * 256 + threadIdx.x) * 4;
    if (i < n) {
        float4 v = *reinterpret_cast<const float4*>(s + i);
        *reinterpret_cast<__half2*>(d + i)     = __floats2half2_rn(v.x, v.y);
        *reinterpret_cast<__half2*>(d + i + 2) = __floats2half2_rn(v.z, v.w);
    }
}

// ---------------------------------------------------------------------------
// Batched float -> half for the six DMODEL x DMODEL weight matrices
// ---------------------------------------------------------------------------
struct Ptr6 { const float* s[6]; };

__global__ __launch_bounds__(256)
void f2h_weights_kernel(Ptr6 src, __half* __restrict__ dst)
{
    const int WW = DMODEL * DMODEL;
    int i = (blockIdx.x * 256 + threadIdx.x) * 4;
    const int mat = i / WW;
    const int off = i - mat * WW;
    const float* sp = src.s[mat] + off;
    __half* dp = dst + (size_t)mat * WW + off;
    float4 v = *reinterpret_cast<const float4*>(sp);
    *reinterpret_cast<__half2*>(dp)     = __floats2half2_rn(v.x, v.y);
    *reinterpret_cast<__half2*>(dp + 2) = __floats2half2_rn(v.z, v.w);
}

// ---------------------------------------------------------------------------
// Zero a float buffer (graph-replay safe scratch reset)
// ---------------------------------------------------------------------------
__global__ __launch_bounds__(256)
void zero_kernel(float* __restrict__ p, int n)
{
    int i = blockIdx.x * 256 + threadIdx.x;
    if (i < n) p[i] = 0.f;
}

// ---------------------------------------------------------------------------
// Fused LayerNorm + exact GELU, fp16 in -> fp16 out (in-place safe)
// ---------------------------------------------------------------------------
__global__ __launch_bounds__(256)
void ln_gelu_kernel(const __half* __restrict__ X, __half* __restrict__ Y,
                    const float* __restrict__ g, const float* __restrict__ be)
{
    const int row = blockIdx.x, tid = threadIdx.x;
    const __half2* x2 = reinterpret_cast<const __half2*>(X + (size_t)row * DMODEL) + tid * 2;
    float2 a0 = __half22float2(x2[0]);
    float2 a1 = __half22float2(x2[1]);
    float s  = a0.x + a0.y + a1.x + a1.y;
    float s2 = a0.x * a0.x + a0.y * a0.y + a1.x * a1.x + a1.y * a1.y;

    __shared__ float shs[32];
    __shared__ float shs2[32];
    __shared__ float bc[2];
#pragma unroll
    for (int o = 16; o > 0; o >>= 1) {
        s  += __shfl_xor_sync(0xffffffffu, s, o);
        s2 += __shfl_xor_sync(0xffffffffu, s2, o);
    }
    if ((tid & 31) == 0) { shs[tid >> 5] = s; shs2[tid >> 5] = s2; }
    __syncthreads();
    if (tid == 0) {
        float a = 0.f, b2 = 0.f;
        for (int i = 0; i < 8; ++i) { a += shs[i]; b2 += shs2[i]; }
        bc[0] = a  * (1.f / DMODEL);
        bc[1] = b2 * (1.f / DMODEL);
    }
    __syncthreads();
    const float mu  = bc[0];
    const float inv = rsqrtf(bc[1] - mu * mu + 1e-5f);

    const float4 gg = *reinterpret_cast<const float4*>(&g[tid * 4]);
    const float4 bb = *reinterpret_cast<const float4*>(&be[tid * 4]);

    float y, o0, o1, o2, o3;
    y = (a0.x - mu) * inv * gg.x + bb.x;  o0 = 0.5f * y * (1.f + erff(y * 0.70710678118654752f));
    y = (a0.y - mu) * inv * gg.y + bb.y;  o1 = 0.5f * y * (1.f + erff(y * 0.70710678118654752f));
    y = (a1.x - mu) * inv * gg.z + bb.z;  o2 = 0.5f * y * (1.f + erff(y * 0.70710678118654752f));
    y = (a1.y - mu) * inv * gg.w + bb.w;  o3 = 0.5f * y * (1.f + erff(y * 0.70710678118654752f));

    __half2* yp = reinterpret_cast<__half2*>(Y + (size_t)row * DMODEL) + tid * 2;
    yp[0] = __floats2half2_rn(o0, o1);
    yp[1] = __floats2half2_rn(o2, o3);
}

// ---------------------------------------------------------------------------
// Row sum-of-squares (fp16 input, fp32 accumulate)
// ---------------------------------------------------------------------------
__global__ __launch_bounds__(256)
void rowsq_kernel(const __half* __restrict__ X, float* __restrict__ out)
{
    const int row = blockIdx.x, tid = threadIdx.x;
    const __half2* x2 = reinterpret_cast<const __half2*>(X + (size_t)row * DMODEL) + tid * 2;
    float2 a0 = __half22float2(x2[0]);
    float2 a1 = __half22float2(x2[1]);
    float s = a0.x * a0.x + a0.y * a0.y + a1.x * a1.x + a1.y * a1.y;
    __shared__ float sh[32];
#pragma unroll
    for (int o = 16; o > 0; o >>= 1) s += __shfl_xor_sync(0xffffffffu, s, o);
    if ((tid & 31) == 0) sh[tid >> 5] = s;
    __syncthreads();
    if (tid == 0) {
        float a = 0.f;
        for (int i = 0; i < 8; ++i) a += sh[i];
        out[row] = a;
    }
}

// ---------------------------------------------------------------------------
// Fused epilogue: similarities -> MLP -> sigmoid.
// learned_sim uses no-max softmax: ls = (1/H) * sum_h exp(s_h) / rowsum[b,h].
// ---------------------------------------------------------------------------
__global__ __launch_bounds__(256)
void fuse_kernel(const float* __restrict__ dot, const __half* __restrict__ scores,
                 const float* __restrict__ qsq, const float* __restrict__ ksq,
                 const float* __restrict__ rowsum,
                 const float* __restrict__ temp,
                 const float* __restrict__ fw1, const float* __restrict__ fb1,
                 const float* __restrict__ fw2, const float* __restrict__ fb2,
                 float* __restrict__ out)
{
    __shared__ float w1[3][FHID];
    __shared__ float b1s[FHID];
    __shared__ float w2s[FHID];
    __shared__ float rinv[NHEAD];
    const int tid = threadIdx.x;
    const int b = blockIdx.y;
    if (tid < 3 * FHID) w1[tid / FHID][tid % FHID] = fw1[tid];
    if (tid < FHID) { b1s[tid] = fb1[tid]; w2s[tid] = fw2[tid]; }
    if (tid < NHEAD) rinv[tid] = 1.f / rowsum[b * NHEAD + tid];
    __syncthreads();

    const int n = blockIdx.x * 256 + tid;
    const float expT = expf(temp[0]);

    const float d  = dot[(size_t)b * NC + n];
    const float qs = qsq[b];
    const float ks = ksq[n];

    const float cs = d * rsqrtf(qs * ks) * expT;
    const float d2 = fmaxf(qs + ks - 2.f * d, 0.f);
    const float eu = 1.f / (1.f + sqrtf(d2));

    float ls = 0.f;
#pragma unroll
    for (int h = 0; h < NHEAD; ++h) {
        const size_t r = (size_t)b * NHEAD + h;
        ls += expf(__half2float(scores[r * NC + n])) * rinv[h];
    }
    ls *= (1.f / NHEAD);

    float logit = fb2[0];
#pragma unroll
    for (int j = 0; j < FHID; ++j) {
        float hj = fmaf(cs, w1[0][j], fmaf(eu, w1[1][j], fmaf(ls, w1[2][j], b1s[j])));
        logit = fmaf(fmaxf(hj, 0.f), w2s[j], logit);
    }
    out[(size_t)b * NC + n] = 1.f / (1.f + expf(-logit));
}

// ---------------------------------------------------------------------------
// Host launcher
// ---------------------------------------------------------------------------
extern "C" void kernel_launch(void* const* d_in, const int* in_sizes, int n_in,
                              void* d_out, int out_size)
{
    const float* query = (const float*)d_in[0];
    const float* cand  = (const float*)d_in[1];
    const float* temp  = (const float*)d_in[2];
    const float* q_w1  = (const float*)d_in[3];
    const float* q_b1  = (const float*)d_in[4];
    const float* q_g   = (const float*)d_in[5];
    const float* q_be  = (const float*)d_in[6];
    const float* q_w2  = (const float*)d_in[7];
    const float* q_b2  = (const float*)d_in[8];
    const float* k_w1  = (const float*)d_in[9];
    const float* k_b1  = (const float*)d_in[10];
    const float* k_g   = (const float*)d_in[11];
    const float* k_be  = (const float*)d_in[12];
    const float* k_w2  = (const float*)d_in[13];
    const float* k_b2  = (const float*)d_in[14];
    const float* wq    = (const float*)d_in[15];
    const float* bq    = (const float*)d_in[16];
    const float* wk    = (const float*)d_in[17];
    const float* bk    = (const float*)d_in[18];
    const float* f_w1  = (const float*)d_in[19];
    const float* f_b1  = (const float*)d_in[20];
    const float* f_w2  = (const float*)d_in[21];
    const float* f_b2  = (const float*)d_in[22];
    float* out = (float*)d_out;

    float*  dotb  = 0;
    float*  qsq   = 0;
    float*  ksq   = 0;
    float*  rs    = 0;
    __half* q16   = 0;
    __half* c16   = 0;
    __half* tmp16 = 0;
    __half* qp16  = 0;
    __half* kp16  = 0;
    __half* qh16  = 0;
    __half* kh16  = 0;
    __half* sc16  = 0;
    __half* w16   = 0;

    cudaGetSymbolAddress((void**)&dotb,  g_dot);
    cudaGetSymbolAddress((void**)&qsq,   g_qsq);
    cudaGetSymbolAddress((void**)&ksq,   g_ksq);
    cudaGetSymbolAddress((void**)&rs,    g_rowsum);
    cudaGetSymbolAddress((void**)&q16,   g_q16);
    cudaGetSymbolAddress((void**)&c16,   g_c16);
    cudaGetSymbolAddress((void**)&tmp16, g_tmp16);
    cudaGetSymbolAddress((void**)&qp16,  g_qp16);
    cudaGetSymbolAddress((void**)&kp16,  g_kp16);
    cudaGetSymbolAddress((void**)&qh16,  g_qh16);
    cudaGetSymbolAddress((void**)&kh16,  g_kh16);
    cudaGetSymbolAddress((void**)&sc16,  g_sc16);
    cudaGetSymbolAddress((void**)&w16,   g_w16);

    const int WW = DMODEL * DMODEL;
    __half* qw1_16 = w16 + 0 * WW;
    __half* qw2_16 = w16 + 1 * WW;
    __half* kw1_16 = w16 + 2 * WW;
    __half* kw2_16 = w16 + 3 * WW;
    __half* wq_16  = w16 + 4 * WW;
    __half* wk_16  = w16 + 5 * WW;

    const int SM_NN = NSTG * (A_STG + BNN_STG) * (int)sizeof(__half);   // 71680 B
    const int SM_NT = NSTG * (A_STG + BNT_STG) * (int)sizeof(__half);   // 73728 B
    cudaFuncSetAttribute(gemm_nn16, cudaFuncAttributeMaxDynamicSharedMemorySize, SM_NN);
    cudaFuncSetAttribute(gemm_nt16, cudaFuncAttributeMaxDynamicSharedMemorySize, SM_NT);

    const dim3 thr(256);
    const dim3 gq(DMODEL / BN, BQ / BM);
    const dim3 gk(DMODEL / BN, NC / BM);
    const float inv_sqrt_hd = 0.08838834764831845f;  // 1/sqrt(128)

    // launch 0: all six weight matrices in one conversion kernel
    Ptr6 wsrc;
    wsrc.s[0] = q_w1; wsrc.s[1] = q_w2; wsrc.s[2] = k_w1;
    wsrc.s[3] = k_w2; wsrc.s[4] = wq;   wsrc.s[5] = wk;
    f2h_weights_kernel<<<(6 * WW) / 1024, thr>>>(wsrc, w16);
    // launches 1-2: input conversions
    f2h_kernel<<<(BQ * DMODEL) / 1024, thr>>>(query, q16, BQ * DMODEL);
    f2h_kernel<<<(NC * DMODEL) / 1024, thr>>>(cand,  c16, NC * DMODEL);

    // launches 3-5: key projection chain — launch 5 is the profiled big GEMM
    gemm_nn16<<<gk, thr, SM_NN>>>(c16, kw1_16, k_b1, (float*)0, tmp16,
                                  DMODEL, DMODEL, DMODEL, DMODEL, 2);
    ln_gelu_kernel<<<NC, thr>>>(tmp16, tmp16, k_g, k_be);
    gemm_nn16<<<gk, thr, SM_NN>>>(tmp16, kw2_16, k_b2, (float*)0, kp16,
                                  DMODEL, DMODEL, DMODEL, DMODEL, 2);

    // query projection chain
    gemm_nn16<<<gq, thr, SM_NN>>>(q16, qw1_16, q_b1, (float*)0, tmp16,
                                  DMODEL, DMODEL, DMODEL, DMODEL, 2);
    ln_gelu_kernel<<<BQ, thr>>>(tmp16, tmp16, q_g, q_be);
    gemm_nn16<<<gq, thr, SM_NN>>>(tmp16, qw2_16, q_b2, (float*)0, qp16,
                                  DMODEL, DMODEL, DMODEL, DMODEL, 2);

    // MHA head projections
    gemm_nn16<<<gk, thr, SM_NN>>>(kp16, wk_16, bk, (float*)0, kh16,
                                  DMODEL, DMODEL, DMODEL, DMODEL, 2);
    gemm_nn16<<<gq, thr, SM_NN>>>(qp16, wq_16, bq, (float*)0, qh16,
                                  DMODEL, DMODEL, DMODEL, DMODEL, 2);

    // norms (fp16 in, fp32 accumulate)
    rowsq_kernel<<<BQ, thr>>>(qp16, qsq);
    rowsq_kernel<<<NC, thr>>>(kp16, ksq);

    // zero the softmax denominators (device globals persist across replays)
    zero_kernel<<<(BQ * NHEAD + 255) / 256, thr>>>(rs, BQ * NHEAD);

    // dot = qp @ kp^T (fp32 out)
    gemm_nt16<<<dim3(NC / BN, BQ / BM, 1), thr, SM_NT>>>(qp16, kp16, dotb, (__half*)0,
                                                         (float*)0,
                                                         DMODEL, DMODEL, DMODEL, NC,
                                                         0, 0, 0, 1.f, 0, 0);

    // per-head scores (fp16 out) + fused sum-of-exp, layout [B][H][N]
    gemm_nt16<<<dim3(NC / BN, BQ / BM, NHEAD), thr, SM_NT>>>(qh16, kh16, (float*)0, sc16,
                                                             rs,
                                                             HDIM, DMODEL, DMODEL, NHEAD * NC,
                                                             HDIM, HDIM, NC, inv_sqrt_hd, 1, 1);

    // fused similarity + MLP + sigmoid
    fuse_kernel<<<dim3(NC / 256, BQ), thr>>>(dotb, sc16, qsq, ksq, rs, temp,
                                             f_w1, f_b1, f_w2, f_b2, out);
}